// round 17
// baseline (speedup 1.0000x reference)
#include <cuda_runtime.h>
#include <cuda_fp16.h>
#include <cstdint>
#include <math.h>

#define BATCH 8
#define SEQ   1024
#define DIM   2048
#define HEADS 16
#define HD    128
#define MROWS (BATCH*SEQ)
#define QSCALE 0.08838834764831845f

// ---- scratch (device globals) ----
__device__ __align__(256) __half g_Qh[MROWS*DIM];
__device__ __align__(256) __half g_Kh[MROWS*DIM];
__device__ __align__(256) __half g_Vh[MROWS*DIM];
__device__ __align__(256) __half g_Cth[MROWS*DIM];
__device__ __align__(256) __half g_Xqh[MROWS*DIM];
__device__ __align__(256) __half g_Xkh[MROWS*DIM];
// weights in NATURAL [K,N] layout, fp16 (no transpose)
__device__ __align__(256) __half g_Wqh[DIM*DIM];
__device__ __align__(256) __half g_Wkh[DIM*DIM];
__device__ __align__(256) __half g_Wvh[DIM*DIM];
__device__ __align__(256) __half g_Woh[DIM*DIM];

// ---- helpers ----
__device__ __forceinline__ unsigned pack_h2(__half a, __half b){ __half2 h=__halves2half2(a,b); return *reinterpret_cast<unsigned*>(&h); }
__device__ __forceinline__ void mma16816(float* c, const unsigned* a, unsigned b0, unsigned b1){
    asm volatile("mma.sync.aligned.m16n8k16.row.col.f32.f16.f16.f32 {%0,%1,%2,%3},{%4,%5,%6,%7},{%8,%9},{%0,%1,%2,%3};\n"
        : "+f"(c[0]),"+f"(c[1]),"+f"(c[2]),"+f"(c[3]) : "r"(a[0]),"r"(a[1]),"r"(a[2]),"r"(a[3]),"r"(b0),"r"(b1));
}
__device__ __forceinline__ uint32_t smem_u32(const void* p){ uint32_t a; asm("{ .reg .u64 t; cvta.to.shared.u64 t, %1; cvt.u32.u64 %0, t; }":"=r"(a):"l"(p)); return a; }
__device__ __forceinline__ void cp16(uint32_t s, const void* g){ asm volatile("cp.async.cg.shared.global [%0], [%1], 16;"::"r"(s),"l"(g)); }
__device__ __forceinline__ void ldsm4(unsigned* r, uint32_t addr){
    asm volatile("ldmatrix.sync.aligned.m8n8.x4.shared.b16 {%0,%1,%2,%3}, [%4];"
        : "=r"(r[0]),"=r"(r[1]),"=r"(r[2]),"=r"(r[3]) : "r"(addr));
}
__device__ __forceinline__ void ldsm4t(unsigned* r, uint32_t addr){
    asm volatile("ldmatrix.sync.aligned.m8n8.x4.trans.shared.b16 {%0,%1,%2,%3}, [%4];"
        : "=r"(r[0]),"=r"(r[1]),"=r"(r[2]),"=r"(r[3]) : "r"(addr));
}
#define CP_COMMIT() asm volatile("cp.async.commit_group;" ::: "memory")
#define CP_WAIT(n)  asm volatile("cp.async.wait_group %0;" :: "n"(n) : "memory")

// =====================================================================
// HMMA 1-term GEMM: C = alpha * Ah @ W  (W natural [K,N] fp16)
// CTA 128x128, warp tile 64x32, BK=64, 3-stage cp.async, ONE sync/iter.
// Invariant: every iteration commits exactly one group -> CP_WAIT(1)
// at iter kt guarantees group kt complete. Prefetch at iter kt targets
// slot (kt+2)%3 == slot(kt-1), whose readers all passed this iter's sync.
// =====================================================================
#define BK 64
#define GLD 72
#define APLANE_B (128*GLD*2)          // 18432 B
#define BPLANE_B (64*256)             // 16384 B
#define STAGE_B (APLANE_B + BPLANE_B) // 34816 B
#define GEMM_SMEM (3*STAGE_B)         // 104448 B (2 CTAs/SM)
#define NKT (DIM/BK)

__device__ __forceinline__ void gemm_body(
    const __half* __restrict__ Ah_g, const __half* __restrict__ Bn_g,
    float* __restrict__ C, __half* __restrict__ Ch,
    float alpha, __half* sm)
{
    const uint32_t sbase = smem_u32(sm);
    const int tid = threadIdx.x, lane = tid & 31, wid = tid >> 5;
    const int wm = wid & 1, wn = wid >> 1;
    const int g = lane >> 2, tig = lane & 3;
    const int t8 = lane >> 3, l7 = lane & 7;
    const int bm = blockIdx.y * 128, bn = blockIdx.x * 128;

    const __half* gsrc[8]; uint32_t soff[8]; int kstep[8];
#pragma unroll
    for (int i = 0; i < 8; i++) {
        if (i < 4) {
            int sub = i * 256 + tid;
            int row = sub >> 3, col = sub & 7;
            gsrc[i] = Ah_g + (size_t)(bm + row) * DIM + col * 8;
            soff[i] = (uint32_t)(row * GLD + col * 8) * 2;
            kstep[i] = BK;
        } else {
            int sub = (i - 4) * 256 + tid;
            int r = sub >> 4, c = sub & 15;
            gsrc[i] = Bn_g + (size_t)r * DIM + bn + c * 8;
            soff[i] = (uint32_t)(APLANE_B + r * 256 + ((c ^ (r & 7)) << 4));
            kstep[i] = BK * DIM;
        }
    }

    float acc[4][4][4];
#pragma unroll
    for (int mf = 0; mf < 4; mf++)
#pragma unroll
        for (int nf = 0; nf < 4; nf++)
#pragma unroll
            for (int r = 0; r < 4; r++) acc[mf][nf][r] = 0.0f;

    const uint32_t a_row0 = (uint32_t)(wm * 64 + (lane & 15));
    const uint32_t a_koff = (uint32_t)((lane >> 4) * 8);

    // prologue: stages 0 and 1, one group each
    {
#pragma unroll
        for (int i = 0; i < 8; i++) cp16(sbase + soff[i], gsrc[i]);
        CP_COMMIT();
#pragma unroll
        for (int i = 0; i < 8; i++) cp16(sbase + STAGE_B + soff[i], gsrc[i] + kstep[i]);
        CP_COMMIT();
    }

    for (int kt = 0; kt < NKT; kt++) {
        CP_WAIT(1);            // group kt complete
        __syncthreads();       // all warps done reading slot (kt-1)
        int pf = kt + 2;
        if (pf < NKT) {
            uint32_t sb2 = sbase + (uint32_t)((pf % 3) * STAGE_B);
#pragma unroll
            for (int i = 0; i < 8; i++) cp16(sb2 + soff[i], gsrc[i] + (size_t)pf * kstep[i]);
        }
        CP_COMMIT();           // exactly one group per iteration (may be empty)

        const uint32_t st = sbase + (uint32_t)((kt % 3) * STAGE_B);
#pragma unroll
        for (int kk = 0; kk < 4; kk++) {
            unsigned ah[4][4];
#pragma unroll
            for (int mf = 0; mf < 4; mf++) {
                uint32_t ra = st + ((a_row0 + mf * 16) * GLD + kk * 16 + a_koff) * 2;
                ldsm4(ah[mf], ra);
            }
            uint32_t kr = (uint32_t)(kk * 16 + ((t8 & 1) << 3) + l7);
            uint32_t sw7 = (kr & 7);
            uint32_t brow = st + APLANE_B + kr * 256;
#pragma unroll
            for (int g2 = 0; g2 < 2; g2++) {
                uint32_t bcol = (uint32_t)(wn * 4 + 2 * g2 + (t8 >> 1));
                unsigned bt[4];
                ldsm4t(bt, brow + ((bcol ^ sw7) << 4));
#pragma unroll
                for (int mf = 0; mf < 4; mf++) {
                    mma16816(acc[mf][2*g2],   ah[mf], bt[0], bt[1]);
                    mma16816(acc[mf][2*g2+1], ah[mf], bt[2], bt[3]);
                }
            }
        }
    }

#pragma unroll
    for (int mf = 0; mf < 4; mf++)
#pragma unroll
        for (int nf = 0; nf < 4; nf++) {
            int row = bm + wm * 64 + mf * 16 + g;
            int col = bn + wn * 32 + nf * 8 + 2 * tig;
            float v0 = acc[mf][nf][0] * alpha, v1 = acc[mf][nf][1] * alpha;
            float v2 = acc[mf][nf][2] * alpha, v3 = acc[mf][nf][3] * alpha;
            if (Ch) {
                *reinterpret_cast<__half2*>(&Ch[(size_t)row*DIM+col])     = __halves2half2(__float2half_rn(v0), __float2half_rn(v1));
                *reinterpret_cast<__half2*>(&Ch[(size_t)(row+8)*DIM+col]) = __halves2half2(__float2half_rn(v2), __float2half_rn(v3));
            } else {
                *reinterpret_cast<float2*>(&C[(size_t)row*DIM+col])       = make_float2(v0,v1);
                *reinterpret_cast<float2*>(&C[(size_t)(row+8)*DIM+col])   = make_float2(v2,v3);
            }
        }
}

__global__ __launch_bounds__(256, 2) void gemm_qkv()
{
    extern __shared__ __half sm[];
    int z = blockIdx.z;
    const __half* A  = (z == 0) ? g_Xqh : g_Xkh;
    const __half* Bn = (z == 0) ? g_Wqh : (z == 1) ? g_Wkh : g_Wvh;
    __half* Ch = (z == 0) ? g_Qh : (z == 1) ? g_Kh : g_Vh;
    float alpha = (z == 0) ? QSCALE : 1.0f;
    gemm_body(A, Bn, nullptr, Ch, alpha, sm);
}

__global__ __launch_bounds__(256, 2) void gemm_o(float* __restrict__ out)
{
    extern __shared__ __half sm[];
    gemm_body(g_Cth, g_Woh, out, nullptr, 1.0f, sm);
}

// one fused elementwise fp32->fp16 conversion for all 6 tensors
__global__ __launch_bounds__(256) void f2h_all(
    const float4* __restrict__ Xq, const float4* __restrict__ Xkv,
    const float4* __restrict__ W0, const float4* __restrict__ W1,
    const float4* __restrict__ W2, const float4* __restrict__ W3)
{
    int z = blockIdx.y;
    const float4* src; __half2* dst; unsigned slice;
    if (z < 4)      { src = Xq;  dst = reinterpret_cast<__half2*>(g_Xqh); slice = z; }
    else if (z < 8) { src = Xkv; dst = reinterpret_cast<__half2*>(g_Xkh); slice = z - 4; }
    else {
        src = (z == 8) ? W0 : (z == 9) ? W1 : (z == 10) ? W2 : W3;
        dst = reinterpret_cast<__half2*>((z == 8) ? g_Wqh : (z == 9) ? g_Wkh : (z == 10) ? g_Wvh : g_Woh);
        slice = 0;
    }
    size_t i = (size_t)slice * 1048576 + (size_t)blockIdx.x * 256 + threadIdx.x;
    float4 v = src[i];
    dst[2*i]   = __halves2half2(__float2half_rn(v.x), __float2half_rn(v.y));
    dst[2*i+1] = __halves2half2(__float2half_rn(v.z), __float2half_rn(v.w));
}

// =====================================================================
// flash2: FA-2. S = Qh*Kh. PV = P-hi*Vh. KT=128.
// Q in dedicated 32KB region; 3 KV stages x 64KB; ONE sync/iter.
// Total smem 224KB (1 CTA/SM).
// =====================================================================
#define FSTG 65536
#define FQ_B 32768
#define FLASH_SMEM (FQ_B + 3*FSTG)   // 229376 B

__global__ __launch_bounds__(256) void flash2()
{
    extern __shared__ char fs[];
    const uint32_t sb = smem_u32(fs);
    const uint32_t kvb = sb + FQ_B;
    const int tid = threadIdx.x, lane = tid & 31, wid = tid >> 5;
    const int g = lane >> 2, tig = lane & 3;
    const int b = blockIdx.z, h = blockIdx.y, qt = blockIdx.x;
    const int t8 = lane >> 3, l7 = lane & 7;

    const size_t qrow0 = (size_t)(b * SEQ + qt * 128);
    const __half* Qg = g_Qh + qrow0 * DIM + h * HD;
    const size_t kvbase = (size_t)b * SEQ * DIM + h * HD;

    const __half* ksrc[16]; uint32_t kdst[16];
#pragma unroll
    for (int i = 0; i < 16; i++) {
        int p = i >> 3;
        int m = tid + 256 * (i & 7);
        int r = m >> 4, c = m & 15;
        const __half* base = (p == 0) ? g_Kh + kvbase : g_Vh + kvbase;
        ksrc[i] = base + (size_t)r * DIM + c * 8;
        kdst[i] = (uint32_t)(p * 32768 + r * 256 + ((c ^ (r & 7)) << 4));
    }

    // group 0: Q + KV stage 0 ; group 1: KV stage 1
#pragma unroll
    for (int i = 0; i < 8; i++) {
        int n = tid + 256 * i;
        int r = n >> 4, c = n & 15;
        cp16(sb + r * 256 + ((c ^ (r & 7)) << 4), Qg + (size_t)r * DIM + c * 8);
    }
#pragma unroll
    for (int i = 0; i < 16; i++) cp16(kvb + kdst[i], ksrc[i]);
    CP_COMMIT();
#pragma unroll
    for (int i = 0; i < 16; i++) cp16(kvb + FSTG + kdst[i], ksrc[i] + (size_t)128 * DIM);
    CP_COMMIT();

    CP_WAIT(1);            // group 0 (Q + stage 0) complete
    __syncthreads();

    unsigned q[8][4];
#pragma unroll
    for (int kk = 0; kk < 8; kk++) {
        uint32_t row = (uint32_t)(wid * 16 + ((t8 & 1) << 3) + l7);
        uint32_t kc  = (uint32_t)(2 * kk + (t8 >> 1));
        ldsm4(q[kk], sb + row * 256 + ((kc ^ (row & 7)) << 4));
    }
    // Q area is never overwritten -> no extra sync needed

    float o[16][4];
#pragma unroll
    for (int i = 0; i < 16; i++) { o[i][0]=o[i][1]=o[i][2]=o[i][3]=0.0f; }
    float m0 = -1e30f, m1 = -1e30f, l0 = 0.0f, l1 = 0.0f;

    for (int kt = 0; kt < SEQ / 128; kt++) {
        if (kt > 0) {
            CP_WAIT(1);         // group kt complete
            __syncthreads();    // all warps done reading slot (kt-1)
        }
        int pf = kt + 2;
        if (pf < SEQ / 128) {
            uint32_t dst = kvb + (uint32_t)((pf % 3) * FSTG);
            size_t koff = (size_t)pf * 128 * DIM;
#pragma unroll
            for (int i = 0; i < 16; i++) cp16(dst + kdst[i], ksrc[i] + koff);
        }
        CP_COMMIT();            // exactly one group per iteration

        const uint32_t st = kvb + (uint32_t)((kt % 3) * FSTG);

        float sc[16][4];
#pragma unroll
        for (int nf = 0; nf < 16; nf++) { sc[nf][0]=sc[nf][1]=sc[nf][2]=sc[nf][3]=0.0f; }
#pragma unroll
        for (int kk = 0; kk < 8; kk++) {
#pragma unroll
            for (int nb = 0; nb < 8; nb++) {
                uint32_t n  = (uint32_t)(nb * 16 + ((t8 >> 1) << 3) + l7);
                uint32_t kc = (uint32_t)(2 * kk + (t8 & 1));
                uint32_t ak = st + n * 256 + ((kc ^ (n & 7)) << 4);
                unsigned bh[4];
                ldsm4(bh, ak);
                mma16816(sc[2*nb],   q[kk], bh[0], bh[1]);
                mma16816(sc[2*nb+1], q[kk], bh[2], bh[3]);
            }
        }

        float r0 = -1e30f, r1 = -1e30f;
#pragma unroll
        for (int nf = 0; nf < 16; nf++) { r0 = fmaxf(r0, fmaxf(sc[nf][0], sc[nf][1])); r1 = fmaxf(r1, fmaxf(sc[nf][2], sc[nf][3])); }
        r0 = fmaxf(r0, __shfl_xor_sync(~0u, r0, 1)); r0 = fmaxf(r0, __shfl_xor_sync(~0u, r0, 2));
        r1 = fmaxf(r1, __shfl_xor_sync(~0u, r1, 1)); r1 = fmaxf(r1, __shfl_xor_sync(~0u, r1, 2));
        float mn0 = fmaxf(m0, r0), mn1 = fmaxf(m1, r1);
        float f0 = __expf(m0 - mn0), f1 = __expf(m1 - mn1);
        m0 = mn0; m1 = mn1;
        float rs0 = 0.0f, rs1 = 0.0f;
#pragma unroll
        for (int nf = 0; nf < 16; nf++) {
            sc[nf][0] = __expf(sc[nf][0] - m0); sc[nf][1] = __expf(sc[nf][1] - m0);
            sc[nf][2] = __expf(sc[nf][2] - m1); sc[nf][3] = __expf(sc[nf][3] - m1);
            rs0 += sc[nf][0] + sc[nf][1]; rs1 += sc[nf][2] + sc[nf][3];
        }
        rs0 += __shfl_xor_sync(~0u, rs0, 1); rs0 += __shfl_xor_sync(~0u, rs0, 2);
        rs1 += __shfl_xor_sync(~0u, rs1, 1); rs1 += __shfl_xor_sync(~0u, rs1, 2);
        l0 = l0 * f0 + rs0; l1 = l1 * f1 + rs1;
#pragma unroll
        for (int nf = 0; nf < 16; nf++) { o[nf][0] *= f0; o[nf][1] *= f0; o[nf][2] *= f1; o[nf][3] *= f1; }

#pragma unroll
        for (int kk2 = 0; kk2 < 8; kk2++) {
            const int j0 = 2*kk2, j1 = 2*kk2 + 1;
            unsigned ah_[4] = {
                pack_h2(__float2half_rn(sc[j0][0]), __float2half_rn(sc[j0][1])),
                pack_h2(__float2half_rn(sc[j0][2]), __float2half_rn(sc[j0][3])),
                pack_h2(__float2half_rn(sc[j1][0]), __float2half_rn(sc[j1][1])),
                pack_h2(__float2half_rn(sc[j1][2]), __float2half_rn(sc[j1][3]))};
            uint32_t kr = (uint32_t)(kk2 * 16 + ((t8 & 1) << 3) + l7);
            uint32_t vrow = st + 32768 + kr * 256;
            uint32_t sw7 = (kr & 7);
#pragma unroll
            for (int na = 0; na < 8; na++) {
                uint32_t nblk = (uint32_t)(2 * na + (t8 >> 1));
                uint32_t av = vrow + ((nblk ^ sw7) << 4);
                unsigned vh[4];
                ldsm4t(vh, av);
                mma16816(o[2*na],   ah_, vh[0], vh[1]);
                mma16816(o[2*na+1], ah_, vh[2], vh[3]);
            }
        }
    }

    float i0 = 1.0f / l0, i1 = 1.0f / l1;
    const size_t row = qrow0 + wid * 16 + g;
    __half* Ch = g_Cth + row * DIM + h * HD;
#pragma unroll
    for (int nf2 = 0; nf2 < 16; nf2++) {
        int c = nf2 * 8 + 2 * tig;
        float v0 = o[nf2][0] * i0, v1 = o[nf2][1] * i0;
        float v2 = o[nf2][2] * i1, v3 = o[nf2][3] * i1;
        *reinterpret_cast<__half2*>(Ch + c)         = __halves2half2(__float2half_rn(v0), __float2half_rn(v1));
        *reinterpret_cast<__half2*>(Ch + 8*DIM + c) = __halves2half2(__float2half_rn(v2), __float2half_rn(v3));
    }
}

// =====================================================================
extern "C" void kernel_launch(void* const* d_in, const int* in_sizes, int n_in,
                              void* d_out, int out_size)
{
    const float* xq  = (const float*)d_in[0];
    const float* xkv = (const float*)d_in[1];
    const float* Wq  = (const float*)d_in[2];
    const float* Wk  = (const float*)d_in[3];
    const float* Wv  = (const float*)d_in[4];
    const float* Wo  = (const float*)d_in[5];
    float* out = (float*)d_out;

    f2h_all<<<dim3(4096, 12), 256>>>((const float4*)xq, (const float4*)xkv,
                                     (const float4*)Wq, (const float4*)Wk,
                                     (const float4*)Wv, (const float4*)Wo);

    cudaFuncSetAttribute(gemm_qkv, cudaFuncAttributeMaxDynamicSharedMemorySize, GEMM_SMEM);
    cudaFuncSetAttribute(gemm_o,   cudaFuncAttributeMaxDynamicSharedMemorySize, GEMM_SMEM);
    gemm_qkv<<<dim3(DIM/128, MROWS/128, 3), 256, GEMM_SMEM>>>();

    cudaFuncSetAttribute(flash2, cudaFuncAttributeMaxDynamicSharedMemorySize, FLASH_SMEM);
    flash2<<<dim3(SEQ/128, HEADS, BATCH), 256, FLASH_SMEM>>>();

    gemm_o<<<dim3(DIM/128, MROWS/128), 256, GEMM_SMEM>>>(out);
}